// round 15
// baseline (speedup 1.0000x reference)
#include <cuda_runtime.h>
#include <cstdint>

#define KC  256      // CLUST_SIZE
#define TPB 128      // threads per CTA; each thread owns rows 2t and 2t+1

typedef unsigned long long u64;

__device__ __forceinline__ u64 pk2(float lo, float hi) {
    union { float2 f; u64 u; } c; c.f = make_float2(lo, hi); return c.u;
}

// Fused packed distance: d = rn( rn(h1+h2) + (-c) ),
//   -c = fma(nz,qz, fma(ny,qy, mul(nx,qx)))   (nx,ny,nz pre-negated).
// Identical op sequence/rounding to the frozen passing arithmetic.
__device__ __forceinline__ void dcalc(u64 nx, u64 ny, u64 nz, u64 hh,
                                      u64 qx, u64 qy, u64 qz, u64 qh,
                                      float& lo, float& hi)
{
    asm("{\n\t"
        ".reg .b64 c, s;\n\t"
        "mul.rn.f32x2 c, %2, %3;\n\t"
        "fma.rn.f32x2 c, %4, %5, c;\n\t"
        "fma.rn.f32x2 c, %6, %7, c;\n\t"
        "add.rn.f32x2 s, %8, %9;\n\t"
        "add.rn.f32x2 s, s, c;\n\t"
        "mov.b64 {%0, %1}, s;\n\t"
        "}"
        : "=f"(lo), "=f"(hi)
        : "l"(nx), "l"(qx), "l"(ny), "l"(qy),
          "l"(nz), "l"(qz), "l"(hh), "l"(qh));
}

__global__ __launch_bounds__(TPB)
void clust_geo_edge_kernel(const float* __restrict__ data,     // [N_VOX, 5]
                           const int*   __restrict__ clusts,   // [N_CLUST, 256]
                           const int*   __restrict__ ei,       // [2, E]
                           float*       __restrict__ out,      // [E, 19]
                           int n_edge)
{
    __shared__ float4 s1[KC];        // cluster-1 rows: {x, y, z, h=0.5*n}
    // cluster-2: pair p (j = 2p, 2p+1) at sT[2p] = {x0,x1,y0,y1},
    //            sT[2p+1] = {z0,z1,h0,h1}.
    __shared__ float4 sT[KC];
    __shared__ float    wv[TPB / 32];      // per-warp min value
    __shared__ unsigned su_row[TPB / 32];  // per-warp min row candidate
    __shared__ unsigned su_j[TPB / 32];    // per-warp min j candidate

    const int e = blockIdx.x;
    const int t = threadIdx.x;
    const int c1 = ei[e];
    const int c2 = ei[n_edge + e];

    // ---- gather; arithmetic bit-identical to the passing rounds:
    //      n via pair02 tree rn(rn(x^2+z^2)+y^2), h = 0.5*n (exact) ----
    float4 r0, r1;
    {
        int2 va = reinterpret_cast<const int2*>(clusts + c1 * KC)[t];
        const float* pa = data + (size_t)va.x * 5;
        const float* pb = data + (size_t)va.y * 5;
        float x = pa[0], y = pa[1], z = pa[2];
        float h = 0.5f * __fadd_rn(__fadd_rn(__fmul_rn(x, x), __fmul_rn(z, z)),
                                   __fmul_rn(y, y));
        r0 = make_float4(x, y, z, h);
        s1[2 * t] = r0;
        x = pb[0]; y = pb[1]; z = pb[2];
        h = 0.5f * __fadd_rn(__fadd_rn(__fmul_rn(x, x), __fmul_rn(z, z)),
                             __fmul_rn(y, y));
        r1 = make_float4(x, y, z, h);
        s1[2 * t + 1] = r1;

        int2 vb = reinterpret_cast<const int2*>(clusts + c2 * KC)[t];
        const float* qa = data + (size_t)vb.x * 5;
        const float* qb = data + (size_t)vb.y * 5;
        float X0 = qa[0], Y0 = qa[1], Z0 = qa[2];
        float H0 = 0.5f * __fadd_rn(__fadd_rn(__fmul_rn(X0, X0), __fmul_rn(Z0, Z0)),
                                    __fmul_rn(Y0, Y0));
        float X1 = qb[0], Y1 = qb[1], Z1 = qb[2];
        float H1 = 0.5f * __fadd_rn(__fadd_rn(__fmul_rn(X1, X1), __fmul_rn(Z1, Z1)),
                                    __fmul_rn(Y1, Y1));
        sT[2 * t + 0] = make_float4(X0, X1, Y0, Y1);
        sT[2 * t + 1] = make_float4(Z0, Z1, H0, H1);
    }
    __syncthreads();

    // Row constants, negated so the fma chain yields -c exactly (rn(-x)=-rn(x)).
    const u64 nx0 = pk2(-r0.x, -r0.x), ny0 = pk2(-r0.y, -r0.y),
              nz0 = pk2(-r0.z, -r0.z), hh0 = pk2( r0.w,  r0.w);
    const u64 nx1 = pk2(-r1.x, -r1.x), ny1 = pk2(-r1.y, -r1.y),
              nz1 = pk2(-r1.z, -r1.z), hh1 = pk2( r1.w,  r1.w);

    const float INF = __int_as_float(0x7f800000);
    float best0 = INF, best1 = INF;     // exact row minima (value only)

    // ===== PHASE 1: min VALUE only — branch-free, SW-pipelined =========
    // Sub-block = 2 j-pairs (4 j) = 4 ulonglong2 (64 B). Explicit register
    // double-buffer: prefetch sub-block k+1 before computing k, so the
    // 29-cyc LDS latency is covered by the 28-inst compute body. Wraparound
    // mask keeps the final prefetch in-bounds without a branch.
    const ulonglong2* base = reinterpret_cast<const ulonglong2*>(sT);

    ulonglong2 cA0 = base[0], cZ0 = base[1], cA1 = base[2], cZ1 = base[3];

#pragma unroll 4
    for (int sb = 0; sb < KC / 4; ++sb) {          // 64 sub-blocks of 4 j
        const ulonglong2* nxt = base + (((sb + 1) & 63) << 2);
        ulonglong2 pA0 = nxt[0], pZ0 = nxt[1], pA1 = nxt[2], pZ1 = nxt[3];

        // row 0
        {
            float a0, a1, b0, b1;
            dcalc(nx0, ny0, nz0, hh0, cA0.x, cA0.y, cZ0.x, cZ0.y, a0, a1);
            dcalc(nx0, ny0, nz0, hh0, cA1.x, cA1.y, cZ1.x, cZ1.y, b0, b1);
            best0 = fminf(best0, fminf(fminf(a0, a1), fminf(b0, b1)));
        }
        // row 1
        {
            float a0, a1, b0, b1;
            dcalc(nx1, ny1, nz1, hh1, cA0.x, cA0.y, cZ0.x, cZ0.y, a0, a1);
            dcalc(nx1, ny1, nz1, hh1, cA1.x, cA1.y, cZ1.x, cZ1.y, b0, b1);
            best1 = fminf(best1, fminf(fminf(a0, a1), fminf(b0, b1)));
        }

        cA0 = pA0; cZ0 = pZ0; cA1 = pA1; cZ1 = pZ1;   // rename under unroll
    }

    // CTA-reduce the min value (order-free: fminf is exact & commutative).
    float bv = fminf(best0, best1);
#pragma unroll
    for (int off = 16; off > 0; off >>= 1)
        bv = fminf(bv, __shfl_down_sync(0xffffffffu, bv, off));
    if ((t & 31) == 0) wv[t >> 5] = bv;
    __syncthreads();
    const float gm = fminf(fminf(wv[0], wv[1]), fminf(wv[2], wv[3]));

    // ===== PHASE 2: parallel first-occurrence index recovery ==============
    // Winning row = lowest row index whose row-min equals gm (float ==,
    // +-0 compare equal, matching argmin equality). All index mins UNSIGNED
    // so the 0xFFFFFFFF sentinel loses to every valid index.
    unsigned rowcand = 0xFFFFFFFFu;
    if (best1 == gm) rowcand = 2u * t + 1u;
    if (best0 == gm) rowcand = 2u * t;         // lower row overwrites
    unsigned rw = __reduce_min_sync(0xffffffffu, rowcand);
    if ((t & 31) == 0) su_row[t >> 5] = rw;
    __syncthreads();
    const unsigned row_win = min(min(su_row[0], su_row[1]),
                                 min(su_row[2], su_row[3]));

    // All 128 threads test one j-pair of the winning row; min flat j wins.
    float4 rv = s1[row_win];
    const u64 nxw = pk2(-rv.x, -rv.x), nyw = pk2(-rv.y, -rv.y),
              nzw = pk2(-rv.z, -rv.z), hhw = pk2( rv.w,  rv.w);
    ulonglong2 abw = base[2 * t], zhw = base[2 * t + 1];
    float lo, hi;
    dcalc(nxw, nyw, nzw, hhw, abw.x, abw.y, zhw.x, zhw.y, lo, hi);
    unsigned jcand = 0xFFFFFFFFu;
    if (hi == gm) jcand = 2u * t + 1u;
    if (lo == gm) jcand = 2u * t;              // lower j overwrites
    unsigned jw = __reduce_min_sync(0xffffffffu, jcand);
    if ((t & 31) == 0) su_j[t >> 5] = jw;
    __syncthreads();

    if (t == 0) {
        unsigned j_win = min(min(su_j[0], su_j[1]), min(su_j[2], su_j[3]));
        int i1 = (int)row_win;
        int i2 = (int)j_win;
        float4 a = s1[i1];
        float4 A = sT[2 * (i2 >> 1) + 0];
        float4 B = sT[2 * (i2 >> 1) + 1];
        int odd = i2 & 1;
        float bx = odd ? A.y : A.x;
        float by = odd ? A.w : A.z;
        float bz = odd ? B.y : B.x;

        float dx = __fsub_rn(a.x, bx);
        float dy = __fsub_rn(a.y, by);
        float dz = __fsub_rn(a.z, bz);
        float lend = __fsqrt_rn(__fadd_rn(__fadd_rn(__fmul_rn(dx, dx),
                                                    __fmul_rn(dz, dz)),
                                          __fmul_rn(dy, dy)));
        float denom = (lend > 0.0f) ? lend : 1.0f;
        float ux = __fdiv_rn(dx, denom);
        float uy = __fdiv_rn(dy, denom);
        float uz = __fdiv_rn(dz, denom);

        float* o = out + (size_t)e * 19;
        o[0]  = a.x; o[1]  = a.y; o[2]  = a.z;   // v1
        o[3]  = bx;  o[4]  = by;  o[5]  = bz;    // v2
        o[6]  = ux;  o[7]  = uy;  o[8]  = uz;    // disp
        o[9]  = lend;
        o[10] = __fmul_rn(ux, ux); o[11] = __fmul_rn(ux, uy); o[12] = __fmul_rn(ux, uz);
        o[13] = __fmul_rn(uy, ux); o[14] = __fmul_rn(uy, uy); o[15] = __fmul_rn(uy, uz);
        o[16] = __fmul_rn(uz, ux); o[17] = __fmul_rn(uz, uy); o[18] = __fmul_rn(uz, uz);
    }
}

extern "C" void kernel_launch(void* const* d_in, const int* in_sizes, int n_in,
                              void* d_out, int out_size)
{
    const float* data   = (const float*)d_in[0];   // [N_VOX, 5] f32
    const int*   clusts = (const int*)  d_in[1];   // [N_CLUST, 256] i32
    const int*   ei     = (const int*)  d_in[2];   // [2, E] i32
    float*       out    = (float*)d_out;           // [E, 19] f32

    int n_edge = in_sizes[2] / 2;
    clust_geo_edge_kernel<<<n_edge, TPB>>>(data, clusts, ei, out, n_edge);
}

// round 17
// speedup vs baseline: 1.0553x; 1.0553x over previous
#include <cuda_runtime.h>
#include <cstdint>

#define KC  256      // CLUST_SIZE
#define TPB 64       // each thread owns rows 4t .. 4t+3

typedef unsigned long long u64;

__device__ __forceinline__ u64 pk2(float lo, float hi) {
    union { float2 f; u64 u; } c; c.f = make_float2(lo, hi); return c.u;
}

// Fused packed distance: d = rn( rn(h1+h2) + (-c) ),
//   -c = fma(nz,qz, fma(ny,qy, mul(nx,qx)))   (nx,ny,nz pre-negated).
// Identical op sequence/rounding to the frozen passing arithmetic; the final
// mov.b64 {lo,hi} is a register pair-split.
__device__ __forceinline__ void dcalc(u64 nx, u64 ny, u64 nz, u64 hh,
                                      u64 qx, u64 qy, u64 qz, u64 qh,
                                      float& lo, float& hi)
{
    asm("{\n\t"
        ".reg .b64 c, s;\n\t"
        "mul.rn.f32x2 c, %2, %3;\n\t"
        "fma.rn.f32x2 c, %4, %5, c;\n\t"
        "fma.rn.f32x2 c, %6, %7, c;\n\t"
        "add.rn.f32x2 s, %8, %9;\n\t"
        "add.rn.f32x2 s, s, c;\n\t"
        "mov.b64 {%0, %1}, s;\n\t"
        "}"
        : "=f"(lo), "=f"(hi)
        : "l"(nx), "l"(qx), "l"(ny), "l"(qy),
          "l"(nz), "l"(qz), "l"(hh), "l"(qh));
}

__global__ __launch_bounds__(TPB)
void clust_geo_edge_kernel(const float* __restrict__ data,     // [N_VOX, 5]
                           const int*   __restrict__ clusts,   // [N_CLUST, 256]
                           const int*   __restrict__ ei,       // [2, E]
                           float*       __restrict__ out,      // [E, 19]
                           int n_edge)
{
    __shared__ float4 s1[KC];        // cluster-1 rows: {x, y, z, h=0.5*n}
    // cluster-2: pair p (j = 2p, 2p+1) at sT[2p] = {x0,x1,y0,y1},
    //            sT[2p+1] = {z0,z1,h0,h1}.
    __shared__ float4 sT[KC];
    __shared__ float    wv[2];       // per-warp min value
    __shared__ unsigned su_row[2];   // per-warp min row candidate
    __shared__ unsigned su_j[2];     // per-warp min j candidate

    const int e = blockIdx.x;
    const int t = threadIdx.x;
    const int c1 = ei[e];
    const int c2 = ei[n_edge + e];

    // ---- gather; arithmetic bit-identical to the passing rounds:
    //      n via pair02 tree rn(rn(x^2+z^2)+y^2), h = 0.5*n (exact) ----
    {
        int4 va = reinterpret_cast<const int4*>(clusts + c1 * KC)[t];
        int idx1[4] = { va.x, va.y, va.z, va.w };
#pragma unroll
        for (int k = 0; k < 4; ++k) {
            const float* pa = data + (size_t)idx1[k] * 5;
            float x = pa[0], y = pa[1], z = pa[2];
            float h = 0.5f * __fadd_rn(__fadd_rn(__fmul_rn(x, x), __fmul_rn(z, z)),
                                       __fmul_rn(y, y));
            s1[4 * t + k] = make_float4(x, y, z, h);
        }

        int4 vb = reinterpret_cast<const int4*>(clusts + c2 * KC)[t];
        int idx2[4] = { vb.x, vb.y, vb.z, vb.w };
        float X[4], Y[4], Z[4], H[4];
#pragma unroll
        for (int k = 0; k < 4; ++k) {
            const float* qa = data + (size_t)idx2[k] * 5;
            X[k] = qa[0]; Y[k] = qa[1]; Z[k] = qa[2];
            H[k] = 0.5f * __fadd_rn(__fadd_rn(__fmul_rn(X[k], X[k]),
                                              __fmul_rn(Z[k], Z[k])),
                                    __fmul_rn(Y[k], Y[k]));
        }
        // pairs p = 2t (j=4t,4t+1) and p = 2t+1 (j=4t+2,4t+3)
        sT[4 * t + 0] = make_float4(X[0], X[1], Y[0], Y[1]);
        sT[4 * t + 1] = make_float4(Z[0], Z[1], H[0], H[1]);
        sT[4 * t + 2] = make_float4(X[2], X[3], Y[2], Y[3]);
        sT[4 * t + 3] = make_float4(Z[2], Z[3], H[2], H[3]);
    }
    __syncthreads();

    // Row constants for rows 4t+k, negated so the fma chain yields -c
    // exactly ( rn(-x) == -rn(x) ).
    u64 nx[4], ny[4], nz[4], hh[4];
#pragma unroll
    for (int k = 0; k < 4; ++k) {
        float4 r = s1[4 * t + k];
        nx[k] = pk2(-r.x, -r.x);
        ny[k] = pk2(-r.y, -r.y);
        nz[k] = pk2(-r.z, -r.z);
        hh[k] = pk2( r.w,  r.w);
    }

    const float INF = __int_as_float(0x7f800000);
    float A0[4] = { INF, INF, INF, INF };   // per-row accum (even lanes)
    float A1[4] = { INF, INF, INF, INF };   // per-row accum (odd lanes)

    const ulonglong2* pt = reinterpret_cast<const ulonglong2*>(sT);

    // ===== PHASE 1: min VALUE only — 4 rows share each load =============
#pragma unroll 4
    for (int it = 0; it < KC / 4; ++it) {      // 64 iters, 2 j-pairs each
        ulonglong2 ab0 = pt[0], zh0 = pt[1];   // pair 2*it
        ulonglong2 ab1 = pt[2], zh1 = pt[3];   // pair 2*it+1
        pt += 4;
#pragma unroll
        for (int k = 0; k < 4; ++k) {
            float l0, h0, l1, h1;
            dcalc(nx[k], ny[k], nz[k], hh[k], ab0.x, ab0.y, zh0.x, zh0.y, l0, h0);
            dcalc(nx[k], ny[k], nz[k], hh[k], ab1.x, ab1.y, zh1.x, zh1.y, l1, h1);
            A0[k] = fminf(A0[k], fminf(l0, l1));
            A1[k] = fminf(A1[k], fminf(h0, h1));
        }
    }

    // Exact per-row minima, then CTA min (fminf exact & commutative).
    float best[4];
#pragma unroll
    for (int k = 0; k < 4; ++k) best[k] = fminf(A0[k], A1[k]);
    float bv = fminf(fminf(best[0], best[1]), fminf(best[2], best[3]));
#pragma unroll
    for (int off = 16; off > 0; off >>= 1)
        bv = fminf(bv, __shfl_down_sync(0xffffffffu, bv, off));
    if ((t & 31) == 0) wv[t >> 5] = bv;
    __syncthreads();
    const float gm = fminf(wv[0], wv[1]);

    // ===== PHASE 2: parallel first-occurrence index recovery ==============
    // Winning row = lowest row index with row-min == gm (float ==; +-0 equal,
    // matching argmin equality). Index mins UNSIGNED so the sentinel loses.
    unsigned rowcand = 0xFFFFFFFFu;
    if (best[3] == gm) rowcand = 4u * t + 3u;
    if (best[2] == gm) rowcand = 4u * t + 2u;
    if (best[1] == gm) rowcand = 4u * t + 1u;
    if (best[0] == gm) rowcand = 4u * t;       // lowest row overwrites
    unsigned rw = __reduce_min_sync(0xffffffffu, rowcand);
    if ((t & 31) == 0) su_row[t >> 5] = rw;
    __syncthreads();
    const unsigned row_win = min(su_row[0], su_row[1]);

    // Each thread tests j = 4t..4t+3 of the winning row; min flat j wins.
    float4 rv = s1[row_win];
    const u64 nxw = pk2(-rv.x, -rv.x), nyw = pk2(-rv.y, -rv.y),
              nzw = pk2(-rv.z, -rv.z), hhw = pk2( rv.w,  rv.w);
    const ulonglong2* base = reinterpret_cast<const ulonglong2*>(sT);
    ulonglong2 abw0 = base[4 * t + 0], zhw0 = base[4 * t + 1];
    ulonglong2 abw1 = base[4 * t + 2], zhw1 = base[4 * t + 3];
    float d0, d1, d2, d3;
    dcalc(nxw, nyw, nzw, hhw, abw0.x, abw0.y, zhw0.x, zhw0.y, d0, d1);
    dcalc(nxw, nyw, nzw, hhw, abw1.x, abw1.y, zhw1.x, zhw1.y, d2, d3);
    unsigned jcand = 0xFFFFFFFFu;
    if (d3 == gm) jcand = 4u * t + 3u;
    if (d2 == gm) jcand = 4u * t + 2u;
    if (d1 == gm) jcand = 4u * t + 1u;
    if (d0 == gm) jcand = 4u * t;              // lowest j overwrites
    unsigned jw = __reduce_min_sync(0xffffffffu, jcand);
    if ((t & 31) == 0) su_j[t >> 5] = jw;
    __syncthreads();

    if (t == 0) {
        unsigned j_win = min(su_j[0], su_j[1]);
        int i1 = (int)row_win;
        int i2 = (int)j_win;
        float4 a = s1[i1];
        float4 A = sT[2 * (i2 >> 1) + 0];
        float4 B = sT[2 * (i2 >> 1) + 1];
        int odd = i2 & 1;
        float bx = odd ? A.y : A.x;
        float by = odd ? A.w : A.z;
        float bz = odd ? B.y : B.x;

        float dx = __fsub_rn(a.x, bx);
        float dy = __fsub_rn(a.y, by);
        float dz = __fsub_rn(a.z, bz);
        float lend = __fsqrt_rn(__fadd_rn(__fadd_rn(__fmul_rn(dx, dx),
                                                    __fmul_rn(dz, dz)),
                                          __fmul_rn(dy, dy)));
        float denom = (lend > 0.0f) ? lend : 1.0f;
        float ux = __fdiv_rn(dx, denom);
        float uy = __fdiv_rn(dy, denom);
        float uz = __fdiv_rn(dz, denom);

        float* o = out + (size_t)e * 19;
        o[0]  = a.x; o[1]  = a.y; o[2]  = a.z;   // v1
        o[3]  = bx;  o[4]  = by;  o[5]  = bz;    // v2
        o[6]  = ux;  o[7]  = uy;  o[8]  = uz;    // disp
        o[9]  = lend;
        o[10] = __fmul_rn(ux, ux); o[11] = __fmul_rn(ux, uy); o[12] = __fmul_rn(ux, uz);
        o[13] = __fmul_rn(uy, ux); o[14] = __fmul_rn(uy, uy); o[15] = __fmul_rn(uy, uz);
        o[16] = __fmul_rn(uz, ux); o[17] = __fmul_rn(uz, uy); o[18] = __fmul_rn(uz, uz);
    }
}

extern "C" void kernel_launch(void* const* d_in, const int* in_sizes, int n_in,
                              void* d_out, int out_size)
{
    const float* data   = (const float*)d_in[0];   // [N_VOX, 5] f32
    const int*   clusts = (const int*)  d_in[1];   // [N_CLUST, 256] i32
    const int*   ei     = (const int*)  d_in[2];   // [2, E] i32
    float*       out    = (float*)d_out;           // [E, 19] f32

    int n_edge = in_sizes[2] / 2;
    clust_geo_edge_kernel<<<n_edge, TPB>>>(data, clusts, ei, out, n_edge);
}